// round 5
// baseline (speedup 1.0000x reference)
#include <cuda_runtime.h>
#include <cstdint>
#include <math.h>

// TISA biased attention, fp32 flash-style, round 5:
//  - GEMM inner loops use packed fma.rn.f32x2 (SASS FFMA2, sm_100+ base ISA)
//    QK^T paired over q-rows; P@V paired over reduction dim k
//  - bias via 512-entry lerp table, no-max shifted softmax (from R3)
//  - 128 threads, 4 CTAs/SM, single wave of 512 CTAs
// B=2, L=2048, H=8, D=64, S=2, F=5. Output fp32 (B,L,H,D).

namespace {
constexpr int Bc = 2, Lc = 2048, Hc = 8, Sc = 2, Fc = 5;
constexpr int TQ = 64, TK = 64;
constexpr int TBL = 512;
constexpr int SMEM_FLOATS = 4096 * 3 + 128 + 128 + TBL * 2;
constexpr int SMEM_BYTES = SMEM_FLOATS * 4;  // 54272
constexpr float DMAX = 1.4142136f;
constexpr float IDXSCALE = (float)(TBL - 1) / DMAX;
constexpr float STEP = DMAX / (float)(TBL - 1);
constexpr float L2E = 1.44269504f;
constexpr float SHIFT = 8.0f;
}

typedef unsigned long long u64t;

__device__ __forceinline__ float fast_sqrtf(float x) {
    float r; asm("sqrt.approx.f32 %0, %1;" : "=f"(r) : "f"(x)); return r;
}
__device__ __forceinline__ float ex2f(float x) {
    float r; asm("ex2.approx.ftz.f32 %0, %1;" : "=f"(r) : "f"(x)); return r;
}
__device__ __forceinline__ u64t splat2(float x) {
    u64t r; const uint32_t u = __float_as_uint(x);
    asm("mov.b64 %0, {%1, %1};" : "=l"(r) : "r"(u)); return r;
}
__device__ __forceinline__ u64t pk2(float lo, float hi) {
    u64t r;
    asm("mov.b64 %0, {%1, %2};" : "=l"(r)
        : "r"(__float_as_uint(lo)), "r"(__float_as_uint(hi)));
    return r;
}
__device__ __forceinline__ float2 unpk2(u64t p) {
    float lo, hi;
    asm("mov.b64 {%0, %1}, %2;" : "=f"(lo), "=f"(hi) : "l"(p));
    return make_float2(lo, hi);
}
__device__ __forceinline__ u64t fma2(u64t a, u64t b, u64t c) {
    u64t d;
    asm("fma.rn.f32x2 %0, %1, %2, %3;" : "=l"(d) : "l"(a), "l"(b), "l"(c));
    return d;
}

__global__ __launch_bounds__(128, 4)
void tisa_attn_kernel(const float* __restrict__ gq,
                      const float* __restrict__ gk,
                      const float* __restrict__ gv,
                      const float* __restrict__ gqs,
                      const float* __restrict__ gks,
                      const float* __restrict__ ga,
                      const float* __restrict__ gb,
                      const float* __restrict__ gc,
                      float* __restrict__ gout)
{
    extern __shared__ float sm[];
    float*  qT   = sm;              // [64 d][64 q] transposed, pre-scaled 1/8
    float*  KP   = sm + 4096;       // phase 1: kT [d][k]; phase 2: P [q][k]
    float*  vsh  = sm + 8192;       // [64 k][64 dv]
    float*  qss  = sm + 12288;      // [64][2]
    float*  kss  = sm + 12416;      // [64][2]
    float2* btab = (float2*)(sm + 12544);  // [512] (value, delta), pre *log2e, -SHIFT

    const int tid = threadIdx.x;
    const int tx  = tid & 15;
    const int ty  = tid >> 4;
    const int q0  = blockIdx.x * TQ;
    const int h   = blockIdx.y;
    const int bb  = blockIdx.z;

    // ---- bias lerp table: (f(d) - SHIFT) * log2e ----
    {
        float ah[Fc], nb[Fc], ch[Fc];
#pragma unroll
        for (int f = 0; f < Fc; f++) {
            ah[f] = ga[h * Fc + f];
            nb[f] = -fabsf(gb[h * Fc + f]);
            ch[f] = gc[h * Fc + f];
        }
        for (int i = tid; i < TBL; i += 128) {
            const float x0 = i * STEP, x1 = x0 + STEP;
            float f0 = 0.f, f1 = 0.f;
#pragma unroll
            for (int f = 0; f < Fc; f++) {
                const float t0 = x0 - ch[f], t1 = x1 - ch[f];
                f0 = fmaf(ah[f], __expf(nb[f] * t0 * t0), f0);
                f1 = fmaf(ah[f], __expf(nb[f] * t1 * t1), f1);
            }
            btab[i] = make_float2((f0 - SHIFT) * L2E, (f1 - f0) * L2E);
        }
    }

    const int row   = tid & 63;
    const int dhalf = tid >> 6;

    // ---- load Q tile transposed (d-major), pre-scaled by 0.125 ----
    {
        const float* q_ptr = gq + ((size_t)((bb * Lc + q0 + row) * Hc + h)) * 64;
#pragma unroll
        for (int i = 0; i < 8; i++) {
            const int d4 = dhalf + i * 2;
            const float4 v = *(const float4*)(q_ptr + d4 * 4);
            qT[(4 * d4 + 0) * 64 + row] = v.x * 0.125f;
            qT[(4 * d4 + 1) * 64 + row] = v.y * 0.125f;
            qT[(4 * d4 + 2) * 64 + row] = v.z * 0.125f;
            qT[(4 * d4 + 3) * 64 + row] = v.w * 0.125f;
        }
        if (tid < 64) {
            qss[tid * 2 + 0] = gqs[(size_t)(bb * Lc + q0 + tid) * Sc + 0];
            qss[tid * 2 + 1] = gqs[(size_t)(bb * Lc + q0 + tid) * Sc + 1];
        }
    }
    __syncthreads();

    float q0s[8], q1s[8];
#pragma unroll
    for (int r = 0; r < 8; r++) {
        q0s[r] = qss[(ty * 8 + r) * 2 + 0];
        q1s[r] = qss[(ty * 8 + r) * 2 + 1];
    }

    float lrow[8];
    u64t  acc2[8][4];   // paired over (even k, odd k); horizontal add at end
#pragma unroll
    for (int r = 0; r < 8; r++) {
        lrow[r] = 0.f;
#pragma unroll
        for (int c = 0; c < 4; c++) acc2[r][c] = 0ull;
    }

    for (int kt = 0; kt < Lc / TK; kt++) {
        const int k0 = kt * TK;
        __syncthreads();

        // ---- load K tile transposed, V row-major, k scale coords ----
        {
            const float* k_ptr = gk + ((size_t)((bb * Lc + k0 + row) * Hc + h)) * 64;
#pragma unroll
            for (int i = 0; i < 8; i++) {
                const int d4 = dhalf + i * 2;
                const float4 v = *(const float4*)(k_ptr + d4 * 4);
                KP[(4 * d4 + 0) * 64 + row] = v.x;
                KP[(4 * d4 + 1) * 64 + row] = v.y;
                KP[(4 * d4 + 2) * 64 + row] = v.z;
                KP[(4 * d4 + 3) * 64 + row] = v.w;
            }
#pragma unroll
            for (int i = 0; i < 8; i++) {
                const int e  = tid + i * 128;
                const int vr = e >> 4, vd4 = e & 15;
                const float4 vv = *(const float4*)(gv +
                    ((size_t)((bb * Lc + k0 + vr) * Hc + h)) * 64 + vd4 * 4);
                *(float4*)(vsh + vr * 64 + vd4 * 4) = vv;
            }
            if (tid < 64) {
                kss[tid * 2 + 0] = gks[(size_t)(bb * Lc + k0 + tid) * Sc + 0];
                kss[tid * 2 + 1] = gks[(size_t)(bb * Lc + k0 + tid) * Sc + 1];
            }
        }
        __syncthreads();

        float k0s[4], k1s[4];
#pragma unroll
        for (int c = 0; c < 4; c++) {
            k0s[c] = kss[(tx * 4 + c) * 2 + 0];
            k1s[c] = kss[(tx * 4 + c) * 2 + 1];
        }

        // ---- S = (Q/8) @ K^T, FFMA2 paired over q-rows ----
        u64t s2[4][4];
#pragma unroll
        for (int rp = 0; rp < 4; rp++)
#pragma unroll
            for (int c = 0; c < 4; c++) s2[rp][c] = 0ull;

#pragma unroll 8
        for (int d = 0; d < 64; d++) {
            const ulonglong2 qa = *(const ulonglong2*)(qT + d * 64 + ty * 8);
            const ulonglong2 qb = *(const ulonglong2*)(qT + d * 64 + ty * 8 + 4);
            const float4 kf = *(const float4*)(KP + d * 64 + tx * 4);
            const u64t qp[4] = {qa.x, qa.y, qb.x, qb.y};
            const u64t kb[4] = {splat2(kf.x), splat2(kf.y), splat2(kf.z), splat2(kf.w)};
#pragma unroll
            for (int rp = 0; rp < 4; rp++)
#pragma unroll
                for (int c = 0; c < 4; c++)
                    s2[rp][c] = fma2(qp[rp], kb[c], s2[rp][c]);
        }

        // unpack scores
        float s[8][4];
#pragma unroll
        for (int rp = 0; rp < 4; rp++)
#pragma unroll
            for (int c = 0; c < 4; c++) {
                const float2 e = unpk2(s2[rp][c]);
                s[2 * rp + 0][c] = e.x;
                s[2 * rp + 1][c] = e.y;
            }

        // ---- bias (table lerp) + shifted exp; accumulate lrow ----
#pragma unroll
        for (int r = 0; r < 8; r++) {
            float psum = 0.f;
#pragma unroll
            for (int c = 0; c < 4; c++) {
                const float dx = q0s[r] - k0s[c];
                const float dy = q1s[r] - k1s[c];
                const float dd = fast_sqrtf(fmaf(dx, dx, dy * dy));
                const float xi = dd * IDXSCALE;
                const int   ii = __float2int_rd(xi);
                const float fr = xi - (float)ii;
                const float2 tb = btab[ii];
                const float p  = ex2f(fmaf(s[r][c], L2E, fmaf(fr, tb.y, tb.x)));
                s[r][c] = p;
                psum += p;
            }
            lrow[r] += psum;
        }

        __syncthreads();  // done reading KP as kT

        // ---- stage P (exp'd scores) into shared, aliasing kT ----
#pragma unroll
        for (int r = 0; r < 8; r++) {
            const float4 pv = make_float4(s[r][0], s[r][1], s[r][2], s[r][3]);
            *(float4*)(KP + (ty * 8 + r) * 64 + tx * 4) = pv;
        }
        __syncthreads();

        // ---- O += P @ V, FFMA2 paired over reduction dim k ----
#pragma unroll 4
        for (int g = 0; g < 16; g++) {
            const float4 v0 = *(const float4*)(vsh + (4 * g + 0) * 64 + tx * 4);
            const float4 v1 = *(const float4*)(vsh + (4 * g + 1) * 64 + tx * 4);
            const float4 v2 = *(const float4*)(vsh + (4 * g + 2) * 64 + tx * 4);
            const float4 v3 = *(const float4*)(vsh + (4 * g + 3) * 64 + tx * 4);
            const u64t vp01[4] = {pk2(v0.x, v1.x), pk2(v0.y, v1.y),
                                  pk2(v0.z, v1.z), pk2(v0.w, v1.w)};
            const u64t vp23[4] = {pk2(v2.x, v3.x), pk2(v2.y, v3.y),
                                  pk2(v2.z, v3.z), pk2(v2.w, v3.w)};
#pragma unroll
            for (int r = 0; r < 8; r++) {
                const ulonglong2 pp =
                    *(const ulonglong2*)(KP + (ty * 8 + r) * 64 + 4 * g);
#pragma unroll
                for (int c = 0; c < 4; c++) {
                    acc2[r][c] = fma2(pp.x, vp01[c], acc2[r][c]);
                    acc2[r][c] = fma2(pp.y, vp23[c], acc2[r][c]);
                }
            }
        }
    }

    // ---- epilogue: lane-reduce lrow, horizontal-add pairs, store ----
#pragma unroll
    for (int r = 0; r < 8; r++) {
        float l = lrow[r];
        l += __shfl_xor_sync(0xffffffffu, l, 1);
        l += __shfl_xor_sync(0xffffffffu, l, 2);
        l += __shfl_xor_sync(0xffffffffu, l, 4);
        l += __shfl_xor_sync(0xffffffffu, l, 8);
        const float inv = 1.f / l;
        float4 o;
        {
            const float2 e0 = unpk2(acc2[r][0]);
            const float2 e1 = unpk2(acc2[r][1]);
            const float2 e2 = unpk2(acc2[r][2]);
            const float2 e3 = unpk2(acc2[r][3]);
            o.x = (e0.x + e0.y) * inv;
            o.y = (e1.x + e1.y) * inv;
            o.z = (e2.x + e2.y) * inv;
            o.w = (e3.x + e3.y) * inv;
        }
        *(float4*)(gout + ((size_t)((bb * Lc + q0 + ty * 8 + r) * Hc + h)) * 64
                   + tx * 4) = o;
    }
}

extern "C" void kernel_launch(void* const* d_in, const int* in_sizes, int n_in,
                              void* d_out, int out_size)
{
    (void)in_sizes; (void)n_in; (void)out_size;
    const float* qs   = (const float*)d_in[0];
    const float* ks   = (const float*)d_in[1];
    const float* vs   = (const float*)d_in[2];
    const float* qs_s = (const float*)d_in[3];
    const float* ks_s = (const float*)d_in[4];
    const float* a    = (const float*)d_in[5];
    const float* b    = (const float*)d_in[6];
    const float* c    = (const float*)d_in[7];
    float* out = (float*)d_out;

    cudaFuncSetAttribute(tisa_attn_kernel,
                         cudaFuncAttributeMaxDynamicSharedMemorySize, SMEM_BYTES);

    dim3 grid(Lc / TQ, Hc, Bc);   // 512 CTAs, one wave at occ 4
    tisa_attn_kernel<<<grid, 128, SMEM_BYTES>>>(qs, ks, vs, qs_s, ks_s,
                                                a, b, c, out);
}

// round 7
// speedup vs baseline: 1.0459x; 1.0459x over previous
#include <cuda_runtime.h>
#include <cstdint>
#include <math.h>

// TISA biased attention, fp32 flash-style, round 6:
//  FFMA2 (fma.rn.f32x2) in both GEMMs, but with NO permanent u64 state:
//   - QK^T: pair over q-rows (natural LDS pairs), splat k (2 MOV each)
//   - P@V : pair over reduction k; P pairs natural from shared; V pairs packed
//           per group; TRANSIENT u64 partials collapsed into fp32 accO per tile
//  occ target 3 (no min-blocks bound) -> no spills; 1.15 waves acceptable.
// B=2, L=2048, H=8, D=64, S=2, F=5. Output fp32 (B,L,H,D).

namespace {
constexpr int Bc = 2, Lc = 2048, Hc = 8, Sc = 2, Fc = 5;
constexpr int TQ = 64, TK = 64;
constexpr int TBL = 512;
constexpr int SMEM_FLOATS = 4096 * 3 + 128 + 128 + TBL * 2;
constexpr int SMEM_BYTES = SMEM_FLOATS * 4;  // 54272
constexpr float DMAX = 1.4142136f;
constexpr float IDXSCALE = (float)(TBL - 1) / DMAX;
constexpr float STEP = DMAX / (float)(TBL - 1);
constexpr float L2E = 1.44269504f;
constexpr float SHIFT = 8.0f;
}

typedef unsigned long long u64t;

__device__ __forceinline__ float fast_sqrtf(float x) {
    float r; asm("sqrt.approx.f32 %0, %1;" : "=f"(r) : "f"(x)); return r;
}
__device__ __forceinline__ float ex2f(float x) {
    float r; asm("ex2.approx.ftz.f32 %0, %1;" : "=f"(r) : "f"(x)); return r;
}
__device__ __forceinline__ u64t splat2(float x) {
    u64t r; const uint32_t u = __float_as_uint(x);
    asm("mov.b64 %0, {%1, %1};" : "=l"(r) : "r"(u)); return r;
}
__device__ __forceinline__ u64t pk2(float lo, float hi) {
    u64t r;
    asm("mov.b64 %0, {%1, %2};" : "=l"(r)
        : "r"(__float_as_uint(lo)), "r"(__float_as_uint(hi)));
    return r;
}
__device__ __forceinline__ float2 unpk2(u64t p) {
    float lo, hi;
    asm("mov.b64 {%0, %1}, %2;" : "=f"(lo), "=f"(hi) : "l"(p));
    return make_float2(lo, hi);
}
__device__ __forceinline__ u64t fma2(u64t a, u64t b, u64t c) {
    u64t d;
    asm("fma.rn.f32x2 %0, %1, %2, %3;" : "=l"(d) : "l"(a), "l"(b), "l"(c));
    return d;
}

__global__ __launch_bounds__(128)
void tisa_attn_kernel(const float* __restrict__ gq,
                      const float* __restrict__ gk,
                      const float* __restrict__ gv,
                      const float* __restrict__ gqs,
                      const float* __restrict__ gks,
                      const float* __restrict__ ga,
                      const float* __restrict__ gb,
                      const float* __restrict__ gc,
                      float* __restrict__ gout)
{
    extern __shared__ float sm[];
    float*  qT   = sm;              // [64 d][64 q] transposed, pre-scaled 1/8
    float*  KP   = sm + 4096;       // phase 1: kT [d][k]; phase 2: P [q][k]
    float*  vsh  = sm + 8192;       // [64 k][64 dv]
    float*  qss  = sm + 12288;      // [64][2]
    float*  kss  = sm + 12416;      // [64][2]
    float2* btab = (float2*)(sm + 12544);  // [512] (value, delta) *log2e, -SHIFT

    const int tid = threadIdx.x;
    const int tx  = tid & 15;
    const int ty  = tid >> 4;
    const int q0  = blockIdx.x * TQ;
    const int h   = blockIdx.y;
    const int bb  = blockIdx.z;

    // ---- bias lerp table: (f(d) - SHIFT) * log2e ----
    {
        float ah[Fc], nb[Fc], ch[Fc];
#pragma unroll
        for (int f = 0; f < Fc; f++) {
            ah[f] = ga[h * Fc + f];
            nb[f] = -fabsf(gb[h * Fc + f]);
            ch[f] = gc[h * Fc + f];
        }
        for (int i = tid; i < TBL; i += 128) {
            const float x0 = i * STEP, x1 = x0 + STEP;
            float f0 = 0.f, f1 = 0.f;
#pragma unroll
            for (int f = 0; f < Fc; f++) {
                const float t0 = x0 - ch[f], t1 = x1 - ch[f];
                f0 = fmaf(ah[f], __expf(nb[f] * t0 * t0), f0);
                f1 = fmaf(ah[f], __expf(nb[f] * t1 * t1), f1);
            }
            btab[i] = make_float2((f0 - SHIFT) * L2E, (f1 - f0) * L2E);
        }
    }

    const int row   = tid & 63;
    const int dhalf = tid >> 6;

    // ---- load Q tile transposed (d-major), pre-scaled by 0.125 ----
    {
        const float* q_ptr = gq + ((size_t)((bb * Lc + q0 + row) * Hc + h)) * 64;
#pragma unroll
        for (int i = 0; i < 8; i++) {
            const int d4 = dhalf + i * 2;
            const float4 v = *(const float4*)(q_ptr + d4 * 4);
            qT[(4 * d4 + 0) * 64 + row] = v.x * 0.125f;
            qT[(4 * d4 + 1) * 64 + row] = v.y * 0.125f;
            qT[(4 * d4 + 2) * 64 + row] = v.z * 0.125f;
            qT[(4 * d4 + 3) * 64 + row] = v.w * 0.125f;
        }
        if (tid < 64) {
            qss[tid * 2 + 0] = gqs[(size_t)(bb * Lc + q0 + tid) * Sc + 0];
            qss[tid * 2 + 1] = gqs[(size_t)(bb * Lc + q0 + tid) * Sc + 1];
        }
    }
    __syncthreads();

    float q0s[8], q1s[8];
#pragma unroll
    for (int r = 0; r < 8; r++) {
        q0s[r] = qss[(ty * 8 + r) * 2 + 0];
        q1s[r] = qss[(ty * 8 + r) * 2 + 1];
    }

    float lrow[8];
    float accO[8][4];   // fp32 permanent accumulator (32 regs, like R3)
#pragma unroll
    for (int r = 0; r < 8; r++) {
        lrow[r] = 0.f;
#pragma unroll
        for (int c = 0; c < 4; c++) accO[r][c] = 0.f;
    }

    for (int kt = 0; kt < Lc / TK; kt++) {
        const int k0 = kt * TK;
        __syncthreads();

        // ---- load K tile transposed, V row-major, k scale coords ----
        {
            const float* k_ptr = gk + ((size_t)((bb * Lc + k0 + row) * Hc + h)) * 64;
#pragma unroll
            for (int i = 0; i < 8; i++) {
                const int d4 = dhalf + i * 2;
                const float4 v = *(const float4*)(k_ptr + d4 * 4);
                KP[(4 * d4 + 0) * 64 + row] = v.x;
                KP[(4 * d4 + 1) * 64 + row] = v.y;
                KP[(4 * d4 + 2) * 64 + row] = v.z;
                KP[(4 * d4 + 3) * 64 + row] = v.w;
            }
#pragma unroll
            for (int i = 0; i < 8; i++) {
                const int e  = tid + i * 128;
                const int vr = e >> 4, vd4 = e & 15;
                const float4 vv = *(const float4*)(gv +
                    ((size_t)((bb * Lc + k0 + vr) * Hc + h)) * 64 + vd4 * 4);
                *(float4*)(vsh + vr * 64 + vd4 * 4) = vv;
            }
            if (tid < 64) {
                kss[tid * 2 + 0] = gks[(size_t)(bb * Lc + k0 + tid) * Sc + 0];
                kss[tid * 2 + 1] = gks[(size_t)(bb * Lc + k0 + tid) * Sc + 1];
            }
        }
        __syncthreads();

        float k0s[4], k1s[4];
#pragma unroll
        for (int c = 0; c < 4; c++) {
            k0s[c] = kss[(tx * 4 + c) * 2 + 0];
            k1s[c] = kss[(tx * 4 + c) * 2 + 1];
        }

        // ---- S = (Q/8) @ K^T, FFMA2 paired over q-rows (transient s2) ----
        u64t s2[4][4];
#pragma unroll
        for (int rp = 0; rp < 4; rp++)
#pragma unroll
            for (int c = 0; c < 4; c++) s2[rp][c] = 0ull;

#pragma unroll 8
        for (int d = 0; d < 64; d++) {
            const ulonglong2 qa = *(const ulonglong2*)(qT + d * 64 + ty * 8);
            const ulonglong2 qb = *(const ulonglong2*)(qT + d * 64 + ty * 8 + 4);
            const float4 kf = *(const float4*)(KP + d * 64 + tx * 4);
            const u64t qp[4] = {qa.x, qa.y, qb.x, qb.y};
            const u64t kb[4] = {splat2(kf.x), splat2(kf.y),
                                splat2(kf.z), splat2(kf.w)};
#pragma unroll
            for (int rp = 0; rp < 4; rp++)
#pragma unroll
                for (int c = 0; c < 4; c++)
                    s2[rp][c] = fma2(qp[rp], kb[c], s2[rp][c]);
        }

        // unpack scores (register-pair aliases; s2 dies here)
        float s[8][4];
#pragma unroll
        for (int rp = 0; rp < 4; rp++)
#pragma unroll
            for (int c = 0; c < 4; c++) {
                const float2 e = unpk2(s2[rp][c]);
                s[2 * rp + 0][c] = e.x;
                s[2 * rp + 1][c] = e.y;
            }

        // ---- bias (table lerp) + shifted exp; accumulate lrow ----
#pragma unroll
        for (int r = 0; r < 8; r++) {
            float psum = 0.f;
#pragma unroll
            for (int c = 0; c < 4; c++) {
                const float dx = q0s[r] - k0s[c];
                const float dy = q1s[r] - k1s[c];
                const float dd = fast_sqrtf(fmaf(dx, dx, dy * dy));
                const float xi = dd * IDXSCALE;
                const int   ii = __float2int_rd(xi);
                const float fr = xi - (float)ii;
                const float2 tb = btab[ii];
                const float p  = ex2f(fmaf(s[r][c], L2E, fmaf(fr, tb.y, tb.x)));
                s[r][c] = p;
                psum += p;
            }
            lrow[r] += psum;
        }

        __syncthreads();  // done reading KP as kT

        // ---- stage P into shared, aliasing kT ----
#pragma unroll
        for (int r = 0; r < 8; r++) {
            const float4 pv = make_float4(s[r][0], s[r][1], s[r][2], s[r][3]);
            *(float4*)(KP + (ty * 8 + r) * 64 + tx * 4) = pv;
        }
        __syncthreads();

        // ---- O += P @ V, FFMA2 paired over k; TRANSIENT t2, collapse/tile ----
        u64t t2[8][4];
#pragma unroll
        for (int r = 0; r < 8; r++)
#pragma unroll
            for (int c = 0; c < 4; c++) t2[r][c] = 0ull;

#pragma unroll 4
        for (int g = 0; g < 16; g++) {
            const float4 v0 = *(const float4*)(vsh + (4 * g + 0) * 64 + tx * 4);
            const float4 v1 = *(const float4*)(vsh + (4 * g + 1) * 64 + tx * 4);
            const float4 v2 = *(const float4*)(vsh + (4 * g + 2) * 64 + tx * 4);
            const float4 v3 = *(const float4*)(vsh + (4 * g + 3) * 64 + tx * 4);
            const u64t vp01[4] = {pk2(v0.x, v1.x), pk2(v0.y, v1.y),
                                  pk2(v0.z, v1.z), pk2(v0.w, v1.w)};
            const u64t vp23[4] = {pk2(v2.x, v3.x), pk2(v2.y, v3.y),
                                  pk2(v2.z, v3.z), pk2(v2.w, v3.w)};
#pragma unroll
            for (int r = 0; r < 8; r++) {
                const ulonglong2 pp =
                    *(const ulonglong2*)(KP + (ty * 8 + r) * 64 + 4 * g);
#pragma unroll
                for (int c = 0; c < 4; c++) {
                    t2[r][c] = fma2(pp.x, vp01[c], t2[r][c]);
                    t2[r][c] = fma2(pp.y, vp23[c], t2[r][c]);
                }
            }
        }
        // collapse pairs into fp32 accumulator (t2 dies here)
#pragma unroll
        for (int r = 0; r < 8; r++)
#pragma unroll
            for (int c = 0; c < 4; c++) {
                const float2 e = unpk2(t2[r][c]);
                accO[r][c] += e.x + e.y;
            }
    }

    // ---- epilogue: lane-reduce lrow, normalize, store ----
#pragma unroll
    for (int r = 0; r < 8; r++) {
        float l = lrow[r];
        l += __shfl_xor_sync(0xffffffffu, l, 1);
        l += __shfl_xor_sync(0xffffffffu, l, 2);
        l += __shfl_xor_sync(0xffffffffu, l, 4);
        l += __shfl_xor_sync(0xffffffffu, l, 8);
        const float inv = 1.f / l;
        const float4 o = make_float4(accO[r][0] * inv, accO[r][1] * inv,
                                     accO[r][2] * inv, accO[r][3] * inv);
        *(float4*)(gout + ((size_t)((bb * Lc + q0 + ty * 8 + r) * Hc + h)) * 64
                   + tx * 4) = o;
    }
}

extern "C" void kernel_launch(void* const* d_in, const int* in_sizes, int n_in,
                              void* d_out, int out_size)
{
    (void)in_sizes; (void)n_in; (void)out_size;
    const float* qs   = (const float*)d_in[0];
    const float* ks   = (const float*)d_in[1];
    const float* vs   = (const float*)d_in[2];
    const float* qs_s = (const float*)d_in[3];
    const float* ks_s = (const float*)d_in[4];
    const float* a    = (const float*)d_in[5];
    const float* b    = (const float*)d_in[6];
    const float* c    = (const float*)d_in[7];
    float* out = (float*)d_out;

    cudaFuncSetAttribute(tisa_attn_kernel,
                         cudaFuncAttributeMaxDynamicSharedMemorySize, SMEM_BYTES);

    dim3 grid(Lc / TQ, Hc, Bc);   // 512 CTAs
    tisa_attn_kernel<<<grid, 128, SMEM_BYTES>>>(qs, ks, vs, qs_s, ks_s,
                                                a, b, c, out);
}

// round 8
// speedup vs baseline: 2.0589x; 1.9686x over previous
#include <cuda_runtime.h>
#include <cstdint>
#include <math.h>

// TISA biased attention, round 7: bf16 mma.sync (base-ISA tensor cores).
//  - S = Q@K^T and O += P@V via mma.sync.m16n8k16.bf16, 3-term hi/lo split
//  - P converts C-frag -> A-frag entirely in registers (no smem roundtrip)
//  - V B-frags via ldmatrix.x4.trans (no transpose staging)
//  - XOR-swizzled bf16 smem tiles, conflict-free ldmatrix
//  - no-max shifted softmax (R3), bias via 512-entry lerp table
// B=2, L=2048, H=8, D=64, S=2, F=5. Output fp32 (B,L,H,D).

namespace {
constexpr int Lc = 2048, Hc = 8, Fc = 5;
constexpr int TQ = 64, TK = 64;
constexpr int TBL = 512;
constexpr int OFF_KH = 0;          // [64 k][64 d] bf16 swizzled (8192 B)
constexpr int OFF_KL = 8192;
constexpr int OFF_VH = 16384;      // [64 k][64 dv] bf16 swizzled
constexpr int OFF_VL = 24576;
constexpr int OFF_KSS = 32768;     // 64 x float2
constexpr int OFF_BTB = 33280;     // 512 x float2
constexpr int SMEM_BYTES = 37376;
constexpr float DMAX = 1.4142136f;
constexpr float IDXSCALE = (float)(TBL - 1) / DMAX;
constexpr float STEP = DMAX / (float)(TBL - 1);
constexpr float L2E = 1.44269504f;
constexpr float SHIFT = 8.0f;
}

__device__ __forceinline__ uint32_t smem_u32(const void* p) {
    uint32_t a;
    asm("{ .reg .u64 t; cvta.to.shared.u64 t, %1; cvt.u32.u64 %0, t; }"
        : "=r"(a) : "l"(p));
    return a;
}
__device__ __forceinline__ float fast_sqrtf(float x) {
    float r; asm("sqrt.approx.f32 %0, %1;" : "=f"(r) : "f"(x)); return r;
}
__device__ __forceinline__ float ex2f(float x) {
    float r; asm("ex2.approx.ftz.f32 %0, %1;" : "=f"(r) : "f"(x)); return r;
}
// pack two f32 into bf16x2: low half = a, high half = b
__device__ __forceinline__ uint32_t pack2(float a, float b) {
    uint32_t r; asm("cvt.rn.bf16x2.f32 %0, %1, %2;" : "=r"(r) : "f"(b), "f"(a));
    return r;
}
__device__ __forceinline__ float lo_f(uint32_t p) { return __uint_as_float(p << 16); }
__device__ __forceinline__ float hi_f(uint32_t p) { return __uint_as_float(p & 0xffff0000u); }

__device__ __forceinline__ void ldmx4(uint32_t& r0, uint32_t& r1,
                                      uint32_t& r2, uint32_t& r3, uint32_t addr) {
    asm volatile("ldmatrix.sync.aligned.m8n8.x4.shared.b16 {%0,%1,%2,%3}, [%4];"
                 : "=r"(r0), "=r"(r1), "=r"(r2), "=r"(r3) : "r"(addr));
}
__device__ __forceinline__ void ldmx4t(uint32_t& r0, uint32_t& r1,
                                       uint32_t& r2, uint32_t& r3, uint32_t addr) {
    asm volatile("ldmatrix.sync.aligned.m8n8.x4.trans.shared.b16 {%0,%1,%2,%3}, [%4];"
                 : "=r"(r0), "=r"(r1), "=r"(r2), "=r"(r3) : "r"(addr));
}
__device__ __forceinline__ void mma16816(float* c, const uint32_t* a,
                                         const uint32_t b0, const uint32_t b1) {
    asm volatile("mma.sync.aligned.m16n8k16.row.col.f32.bf16.bf16.f32 "
                 "{%0,%1,%2,%3}, {%4,%5,%6,%7}, {%8,%9}, {%0,%1,%2,%3};"
                 : "+f"(c[0]), "+f"(c[1]), "+f"(c[2]), "+f"(c[3])
                 : "r"(a[0]), "r"(a[1]), "r"(a[2]), "r"(a[3]), "r"(b0), "r"(b1));
}

__global__ __launch_bounds__(128)
void tisa_attn_kernel(const float* __restrict__ gq,
                      const float* __restrict__ gk,
                      const float* __restrict__ gv,
                      const float* __restrict__ gqs,
                      const float* __restrict__ gks,
                      const float* __restrict__ ga,
                      const float* __restrict__ gb,
                      const float* __restrict__ gc,
                      float* __restrict__ gout)
{
    extern __shared__ __align__(1024) char smc[];
    const uint32_t sbase = smem_u32(smc);
    const int tid  = threadIdx.x;
    const int w    = tid >> 5;
    const int lane = tid & 31;
    const int g    = lane >> 2;   // C-frag row group
    const int tig  = lane & 3;    // C-frag col group
    const int q0   = blockIdx.x * TQ;
    const int h    = blockIdx.y;
    const int bb   = blockIdx.z;

    // ldmatrix lane-role precompute (swizzle xor reduces to mrow<<4)
    const int mrow = lane & 7, msel = lane >> 3;
    const int sx   = mrow << 4;
    const int pa_row = ((msel & 1) << 3) + mrow;   // A-frag & V-trans pattern
    const int pa_c   = (msel >> 1) << 4;
    const int pb_row = ((msel >> 1) << 3) + mrow;  // K B-frag pattern
    const int pb_c   = (msel & 1) << 4;

    // ---- bias lerp table: (f(d) - SHIFT) * log2e ----
    {
        float2* btab = (float2*)(smc + OFF_BTB);
        float ah[Fc], nb[Fc], ch[Fc];
#pragma unroll
        for (int f = 0; f < Fc; f++) {
            ah[f] = ga[h * Fc + f];
            nb[f] = -fabsf(gb[h * Fc + f]);
            ch[f] = gc[h * Fc + f];
        }
        for (int i = tid; i < TBL; i += 128) {
            const float x0 = i * STEP, x1 = x0 + STEP;
            float f0 = 0.f, f1 = 0.f;
#pragma unroll
            for (int f = 0; f < Fc; f++) {
                const float t0 = x0 - ch[f], t1 = x1 - ch[f];
                f0 = fmaf(ah[f], __expf(nb[f] * t0 * t0), f0);
                f1 = fmaf(ah[f], __expf(nb[f] * t1 * t1), f1);
            }
            btab[i] = make_float2((f0 - SHIFT) * L2E, (f1 - f0) * L2E);
        }
    }

    // ---- stage Q (scaled 1/8) as bf16 hi/lo into KH/KL (aliased) ----
    const int crow = tid & 63;          // converter row
    const int chalf = (tid >> 6) * 32;  // converter d-offset
    {
        const float* qp = gq + ((size_t)((bb * Lc + q0 + crow) * Hc + h)) * 64 + chalf;
#pragma unroll
        for (int jj = 0; jj < 8; jj++) {
            float4 v = *(const float4*)(qp + jj * 4);
            v.x *= 0.125f; v.y *= 0.125f; v.z *= 0.125f; v.w *= 0.125f;
            const uint32_t h0 = pack2(v.x, v.y), h1 = pack2(v.z, v.w);
            const uint32_t l0 = pack2(v.x - lo_f(h0), v.y - hi_f(h0));
            const uint32_t l1 = pack2(v.z - lo_f(h1), v.w - hi_f(h1));
            const int off = crow * 128 + ((chalf * 2 + jj * 8) ^ ((crow & 7) << 4));
            *(uint2*)(smc + OFF_KH + off) = make_uint2(h0, h1);
            *(uint2*)(smc + OFF_KL + off) = make_uint2(l0, l1);
        }
    }
    __syncthreads();

    // ---- Q fragments (persistent): 4 d-chunks x 4 regs, hi & lo ----
    uint32_t qh[4][4], ql[4][4];
#pragma unroll
    for (int j = 0; j < 4; j++) {
        const uint32_t ad = sbase + OFF_KH + (16 * w + pa_row) * 128 + ((32 * j + pa_c) ^ sx);
        ldmx4(qh[j][0], qh[j][1], qh[j][2], qh[j][3], ad);
        const uint32_t al = sbase + OFF_KL + (16 * w + pa_row) * 128 + ((32 * j + pa_c) ^ sx);
        ldmx4(ql[j][0], ql[j][1], ql[j][2], ql[j][3], al);
    }

    // ---- per-thread q-row scale coords (rows 16w+g and +8) ----
    const int qrow = q0 + 16 * w + g;
    const float2 qc0 = *(const float2*)(gqs + (size_t)(bb * Lc + qrow) * 2);
    const float2 qc1 = *(const float2*)(gqs + (size_t)(bb * Lc + qrow + 8) * 2);

    float accO[8][4];
#pragma unroll
    for (int n = 0; n < 8; n++)
#pragma unroll
        for (int e = 0; e < 4; e++) accO[n][e] = 0.f;
    float lrow0 = 0.f, lrow1 = 0.f;

    const float2* kss2 = (const float2*)(smc + OFF_KSS);
    const float2* btab = (const float2*)(smc + OFF_BTB);

    for (int kt = 0; kt < Lc / TK; kt++) {
        const int k0 = kt * TK;
        __syncthreads();  // prev tile frag reads / Q frag reads complete

        // ---- convert K,V tiles to bf16 hi/lo (swizzled), load k coords ----
        {
            const float* kp = gk + ((size_t)((bb * Lc + k0 + crow) * Hc + h)) * 64 + chalf;
            const float* vp = gv + ((size_t)((bb * Lc + k0 + crow) * Hc + h)) * 64 + chalf;
#pragma unroll
            for (int jj = 0; jj < 8; jj++) {
                const float4 v = *(const float4*)(kp + jj * 4);
                const uint32_t h0 = pack2(v.x, v.y), h1 = pack2(v.z, v.w);
                const uint32_t l0 = pack2(v.x - lo_f(h0), v.y - hi_f(h0));
                const uint32_t l1 = pack2(v.z - lo_f(h1), v.w - hi_f(h1));
                const int off = crow * 128 + ((chalf * 2 + jj * 8) ^ ((crow & 7) << 4));
                *(uint2*)(smc + OFF_KH + off) = make_uint2(h0, h1);
                *(uint2*)(smc + OFF_KL + off) = make_uint2(l0, l1);
            }
#pragma unroll
            for (int jj = 0; jj < 8; jj++) {
                const float4 v = *(const float4*)(vp + jj * 4);
                const uint32_t h0 = pack2(v.x, v.y), h1 = pack2(v.z, v.w);
                const uint32_t l0 = pack2(v.x - lo_f(h0), v.y - hi_f(h0));
                const uint32_t l1 = pack2(v.z - lo_f(h1), v.w - hi_f(h1));
                const int off = crow * 128 + ((chalf * 2 + jj * 8) ^ ((crow & 7) << 4));
                *(uint2*)(smc + OFF_VH + off) = make_uint2(h0, h1);
                *(uint2*)(smc + OFF_VL + off) = make_uint2(l0, l1);
            }
            if (tid < 64)
                ((float2*)(smc + OFF_KSS))[tid] =
                    *(const float2*)(gks + (size_t)(bb * Lc + k0 + tid) * 2);
        }
        __syncthreads();

        // ---- S = Q @ K^T : 8 n-tiles, 4 d-chunks, 3 split terms ----
        float cs[8][4];
#pragma unroll
        for (int n = 0; n < 8; n++)
#pragma unroll
            for (int e = 0; e < 4; e++) cs[n][e] = 0.f;

#pragma unroll
        for (int j = 0; j < 4; j++) {
            uint32_t bh[8][2], bl[8][2];
#pragma unroll
            for (int p = 0; p < 4; p++) {
                const uint32_t ah2 = sbase + OFF_KH + (16 * p + pb_row) * 128
                                     + ((32 * j + pb_c) ^ sx);
                ldmx4(bh[2 * p][0], bh[2 * p][1], bh[2 * p + 1][0], bh[2 * p + 1][1], ah2);
                const uint32_t al2 = sbase + OFF_KL + (16 * p + pb_row) * 128
                                     + ((32 * j + pb_c) ^ sx);
                ldmx4(bl[2 * p][0], bl[2 * p][1], bl[2 * p + 1][0], bl[2 * p + 1][1], al2);
            }
#pragma unroll
            for (int n = 0; n < 8; n++) {
                mma16816(cs[n], qh[j], bh[n][0], bh[n][1]);
                mma16816(cs[n], ql[j], bh[n][0], bh[n][1]);
                mma16816(cs[n], qh[j], bl[n][0], bl[n][1]);
            }
        }

        // ---- bias + shifted exp on C-frags; accumulate row sums ----
        float psum0 = 0.f, psum1 = 0.f;
#pragma unroll
        for (int n = 0; n < 8; n++) {
            const float4 kc = *(const float4*)(kss2 + 8 * n + 2 * tig);
            float bias[4];
            {
                const float dx0 = qc0.x - kc.x, dy0 = qc0.y - kc.y;
                const float dx1 = qc0.x - kc.z, dy1 = qc0.y - kc.w;
                const float dx2 = qc1.x - kc.x, dy2 = qc1.y - kc.y;
                const float dx3 = qc1.x - kc.z, dy3 = qc1.y - kc.w;
                const float dd[4] = {fast_sqrtf(fmaf(dx0, dx0, dy0 * dy0)),
                                     fast_sqrtf(fmaf(dx1, dx1, dy1 * dy1)),
                                     fast_sqrtf(fmaf(dx2, dx2, dy2 * dy2)),
                                     fast_sqrtf(fmaf(dx3, dx3, dy3 * dy3))};
#pragma unroll
                for (int e = 0; e < 4; e++) {
                    const float xi = dd[e] * IDXSCALE;
                    const int   ii = __float2int_rd(xi);
                    const float fr = xi - (float)ii;
                    const float2 tb = btab[ii];
                    bias[e] = fmaf(fr, tb.y, tb.x);
                }
            }
            const float p0 = ex2f(fmaf(cs[n][0], L2E, bias[0]));
            const float p1 = ex2f(fmaf(cs[n][1], L2E, bias[1]));
            const float p2 = ex2f(fmaf(cs[n][2], L2E, bias[2]));
            const float p3 = ex2f(fmaf(cs[n][3], L2E, bias[3]));
            cs[n][0] = p0; cs[n][1] = p1; cs[n][2] = p2; cs[n][3] = p3;
            psum0 += p0 + p1;
            psum1 += p2 + p3;
        }
        lrow0 += psum0;
        lrow1 += psum1;

        // ---- O += P @ V : P frags built in registers from cs ----
#pragma unroll
        for (int j = 0; j < 4; j++) {
            uint32_t vh[8][2], vl[8][2];
#pragma unroll
            for (int p = 0; p < 4; p++) {
                const uint32_t ah2 = sbase + OFF_VH + (16 * j + pa_row) * 128
                                     + ((32 * p + pa_c) ^ sx);
                ldmx4t(vh[2 * p][0], vh[2 * p][1], vh[2 * p + 1][0], vh[2 * p + 1][1], ah2);
                const uint32_t al2 = sbase + OFF_VL + (16 * j + pa_row) * 128
                                     + ((32 * p + pa_c) ^ sx);
                ldmx4t(vl[2 * p][0], vl[2 * p][1], vl[2 * p + 1][0], vl[2 * p + 1][1], al2);
            }
            uint32_t pha[4], pla[4];
            pha[0] = pack2(cs[2 * j][0], cs[2 * j][1]);
            pha[1] = pack2(cs[2 * j][2], cs[2 * j][3]);
            pha[2] = pack2(cs[2 * j + 1][0], cs[2 * j + 1][1]);
            pha[3] = pack2(cs[2 * j + 1][2], cs[2 * j + 1][3]);
            pla[0] = pack2(cs[2 * j][0] - lo_f(pha[0]), cs[2 * j][1] - hi_f(pha[0]));
            pla[1] = pack2(cs[2 * j][2] - lo_f(pha[1]), cs[2 * j][3] - hi_f(pha[1]));
            pla[2] = pack2(cs[2 * j + 1][0] - lo_f(pha[2]), cs[2 * j + 1][1] - hi_f(pha[2]));
            pla[3] = pack2(cs[2 * j + 1][2] - lo_f(pha[3]), cs[2 * j + 1][3] - hi_f(pha[3]));
#pragma unroll
            for (int n = 0; n < 8; n++) {
                mma16816(accO[n], pha, vh[n][0], vh[n][1]);
                mma16816(accO[n], pla, vh[n][0], vh[n][1]);
                mma16816(accO[n], pha, vl[n][0], vl[n][1]);
            }
        }
    }

    // ---- epilogue: reduce row sums over tig lanes, normalize, store ----
    lrow0 += __shfl_xor_sync(0xffffffffu, lrow0, 1);
    lrow0 += __shfl_xor_sync(0xffffffffu, lrow0, 2);
    lrow1 += __shfl_xor_sync(0xffffffffu, lrow1, 1);
    lrow1 += __shfl_xor_sync(0xffffffffu, lrow1, 2);
    const float inv0 = 1.f / lrow0;
    const float inv1 = 1.f / lrow1;

    float* o0 = gout + ((size_t)((bb * Lc + qrow) * Hc + h)) * 64;
    float* o1 = gout + ((size_t)((bb * Lc + qrow + 8) * Hc + h)) * 64;
#pragma unroll
    for (int n = 0; n < 8; n++) {
        const int dv = 8 * n + 2 * tig;
        *(float2*)(o0 + dv) = make_float2(accO[n][0] * inv0, accO[n][1] * inv0);
        *(float2*)(o1 + dv) = make_float2(accO[n][2] * inv1, accO[n][3] * inv1);
    }
}

extern "C" void kernel_launch(void* const* d_in, const int* in_sizes, int n_in,
                              void* d_out, int out_size)
{
    (void)in_sizes; (void)n_in; (void)out_size;
    const float* qs   = (const float*)d_in[0];
    const float* ks   = (const float*)d_in[1];
    const float* vs   = (const float*)d_in[2];
    const float* qs_s = (const float*)d_in[3];
    const float* ks_s = (const float*)d_in[4];
    const float* a    = (const float*)d_in[5];
    const float* b    = (const float*)d_in[6];
    const float* c    = (const float*)d_in[7];
    float* out = (float*)d_out;

    cudaFuncSetAttribute(tisa_attn_kernel,
                         cudaFuncAttributeMaxDynamicSharedMemorySize, SMEM_BYTES);

    dim3 grid(Lc / TQ, Hc, 2);   // (32, 8, 2) = 512 CTAs
    tisa_attn_kernel<<<grid, 128, SMEM_BYTES>>>(qs, ks, vs, qs_s, ks_s,
                                                a, b, c, out);
}

// round 9
// speedup vs baseline: 3.7640x; 1.8281x over previous
#include <cuda_runtime.h>
#include <cstdint>
#include <math.h>

// TISA biased attention, round 8: mma.sync bf16 (R7) + pre-pass split + cp.async
// double-buffered K/V pipeline.
//  - pre-pass kernel converts Q(scaled)/K/V to bf16 hi/lo tiles in GLOBAL memory,
//    already swizzled exactly as ldmatrix wants -> main loop has ZERO convert work
//  - main kernel cp.asyncs 33KB/tile (K,V hi/lo + k coords) into 2 smem buffers,
//    prefetching tile t+2 while computing tile t (fetch latency fully hidden)
//  - 3-term hi/lo split MMAs, in-register P frags, no-max shifted softmax
// B=2, L=2048, H=8, D=64, S=2, F=5. Output fp32 (B,L,H,D).

namespace {
constexpr int Lc = 2048, Hc = 8, Fc = 5;
constexpr int TQ = 64;
constexpr int TBL = 512;
constexpr int BUFS = 33792;            // KH 8K | KL 8K | VH 8K | VL 8K | kss 512 | pad
constexpr int OFF_KSSR = 32768;
constexpr int OFF_BTB = 2 * BUFS;      // 67584
constexpr int SMEM_BYTES = OFF_BTB + TBL * 8;  // 71680 -> 3 CTAs/SM (210KB/228KB)
constexpr float DMAX = 1.4142136f;
constexpr float IDXSCALE = (float)(TBL - 1) / DMAX;
constexpr float STEP = DMAX / (float)(TBL - 1);
constexpr float L2E = 1.44269504f;
constexpr float SHIFT = 8.0f;
}

// [tensor: 0=Q,1=K,2=V][(b*8+h)*32 + tile][hi plane 8192 | lo plane 8192]
__device__ __align__(16) unsigned char gQKV[3][512][16384];

__device__ __forceinline__ uint32_t smem_u32(const void* p) {
    uint32_t a;
    asm("{ .reg .u64 t; cvta.to.shared.u64 t, %1; cvt.u32.u64 %0, t; }"
        : "=r"(a) : "l"(p));
    return a;
}
__device__ __forceinline__ float fast_sqrtf(float x) {
    float r; asm("sqrt.approx.f32 %0, %1;" : "=f"(r) : "f"(x)); return r;
}
__device__ __forceinline__ float ex2f(float x) {
    float r; asm("ex2.approx.ftz.f32 %0, %1;" : "=f"(r) : "f"(x)); return r;
}
__device__ __forceinline__ uint32_t pack2(float a, float b) {
    uint32_t r; asm("cvt.rn.bf16x2.f32 %0, %1, %2;" : "=r"(r) : "f"(b), "f"(a));
    return r;
}
__device__ __forceinline__ float lo_f(uint32_t p) { return __uint_as_float(p << 16); }
__device__ __forceinline__ float hi_f(uint32_t p) { return __uint_as_float(p & 0xffff0000u); }

__device__ __forceinline__ void cp16(uint32_t dst, const void* src) {
    asm volatile("cp.async.cg.shared.global [%0], [%1], 16;"
                 :: "r"(dst), "l"(src) : "memory");
}
__device__ __forceinline__ void cp_commit() {
    asm volatile("cp.async.commit_group;" ::: "memory");
}
template <int N>
__device__ __forceinline__ void cp_wait() {
    asm volatile("cp.async.wait_group %0;" :: "n"(N) : "memory");
}

__device__ __forceinline__ void ldmx4(uint32_t& r0, uint32_t& r1,
                                      uint32_t& r2, uint32_t& r3, uint32_t addr) {
    asm volatile("ldmatrix.sync.aligned.m8n8.x4.shared.b16 {%0,%1,%2,%3}, [%4];"
                 : "=r"(r0), "=r"(r1), "=r"(r2), "=r"(r3) : "r"(addr));
}
__device__ __forceinline__ void ldmx4t(uint32_t& r0, uint32_t& r1,
                                       uint32_t& r2, uint32_t& r3, uint32_t addr) {
    asm volatile("ldmatrix.sync.aligned.m8n8.x4.trans.shared.b16 {%0,%1,%2,%3}, [%4];"
                 : "=r"(r0), "=r"(r1), "=r"(r2), "=r"(r3) : "r"(addr));
}
__device__ __forceinline__ void mma16816(float* c, const uint32_t* a,
                                         const uint32_t b0, const uint32_t b1) {
    asm volatile("mma.sync.aligned.m16n8k16.row.col.f32.bf16.bf16.f32 "
                 "{%0,%1,%2,%3}, {%4,%5,%6,%7}, {%8,%9}, {%0,%1,%2,%3};"
                 : "+f"(c[0]), "+f"(c[1]), "+f"(c[2]), "+f"(c[3])
                 : "r"(a[0]), "r"(a[1]), "r"(a[2]), "r"(a[3]), "r"(b0), "r"(b1));
}

// ---------------- pre-pass: fp32 -> swizzled bf16 hi/lo tiles ----------------
__global__ __launch_bounds__(128)
void tisa_prepass(const float* __restrict__ gq,
                  const float* __restrict__ gk,
                  const float* __restrict__ gv)
{
    __shared__ __align__(16) unsigned char sb[16384];
    const int t3   = blockIdx.y;           // 0=Q,1=K,2=V
    const int idx  = blockIdx.x;           // (b*8+h)*32 + tile
    const int tile = idx & 31;
    const int bh   = idx >> 5;
    const int h    = bh & 7, b = bh >> 3;
    const int tid  = threadIdx.x;
    const int crow = tid & 63;
    const int chalf = (tid >> 6) * 32;

    const float* src = (t3 == 0) ? gq : (t3 == 1) ? gk : gv;
    const float sc = (t3 == 0) ? 0.125f : 1.0f;
    const float* sp = src +
        ((size_t)(((b * Lc + tile * 64 + crow) * Hc) + h)) * 64 + chalf;

#pragma unroll
    for (int jj = 0; jj < 8; jj++) {
        float4 v = *(const float4*)(sp + jj * 4);
        v.x *= sc; v.y *= sc; v.z *= sc; v.w *= sc;
        const uint32_t h0 = pack2(v.x, v.y), h1 = pack2(v.z, v.w);
        const uint32_t l0 = pack2(v.x - lo_f(h0), v.y - hi_f(h0));
        const uint32_t l1 = pack2(v.z - lo_f(h1), v.w - hi_f(h1));
        const int off = crow * 128 + ((chalf * 2 + jj * 8) ^ ((crow & 7) << 4));
        *(uint2*)(sb + off)        = make_uint2(h0, h1);
        *(uint2*)(sb + 8192 + off) = make_uint2(l0, l1);
    }
    __syncthreads();

    uint4* dst = (uint4*)(&gQKV[t3][idx][0]);
    const uint4* s4 = (const uint4*)sb;
#pragma unroll
    for (int i = 0; i < 8; i++)
        dst[tid + 128 * i] = s4[tid + 128 * i];
}

// ------------------------------- main kernel --------------------------------
__global__ __launch_bounds__(128, 3)
void tisa_attn_kernel(const float* __restrict__ gqs,
                      const float* __restrict__ gks,
                      const float* __restrict__ ga,
                      const float* __restrict__ gb,
                      const float* __restrict__ gc,
                      float* __restrict__ gout)
{
    extern __shared__ __align__(1024) char smc[];
    const uint32_t sbase = smem_u32(smc);
    const int tid  = threadIdx.x;
    const int w    = tid >> 5;
    const int lane = tid & 31;
    const int g    = lane >> 2;
    const int tig  = lane & 3;
    const int qt   = blockIdx.x;          // q-tile index (64 rows)
    const int h    = blockIdx.y;
    const int bb   = blockIdx.z;
    const int bh32 = (bb * Hc + h) * 32;

    // ldmatrix lane-role precompute (swizzle xor reduces to mrow<<4)
    const int mrow = lane & 7, msel = lane >> 3;
    const int sx   = mrow << 4;
    const int pa_row = ((msel & 1) << 3) + mrow;
    const int pa_c   = (msel >> 1) << 4;
    const int pb_row = ((msel >> 1) << 3) + mrow;
    const int pb_c   = (msel & 1) << 4;

    // ---- bias lerp table: (f(d) - SHIFT) * log2e ----
    {
        float2* btab = (float2*)(smc + OFF_BTB);
        float ah[Fc], nb[Fc], ch[Fc];
#pragma unroll
        for (int f = 0; f < Fc; f++) {
            ah[f] = ga[h * Fc + f];
            nb[f] = -fabsf(gb[h * Fc + f]);
            ch[f] = gc[h * Fc + f];
        }
        for (int i = tid; i < TBL; i += 128) {
            const float x0 = i * STEP, x1 = x0 + STEP;
            float f0 = 0.f, f1 = 0.f;
#pragma unroll
            for (int f = 0; f < Fc; f++) {
                const float t0 = x0 - ch[f], t1 = x1 - ch[f];
                f0 = fmaf(ah[f], __expf(nb[f] * t0 * t0), f0);
                f1 = fmaf(ah[f], __expf(nb[f] * t1 * t1), f1);
            }
            btab[i] = make_float2((f0 - SHIFT) * L2E, (f1 - f0) * L2E);
        }
    }

    // ---- fetch this CTA's Q tile (bf16 hi/lo, pre-scaled) into buf0 ----
    {
        const unsigned char* qsrc = &gQKV[0][bh32 + qt][0];
#pragma unroll
        for (int i = 0; i < 8; i++)
            cp16(sbase + (tid + 128 * i) * 16, qsrc + (tid + 128 * i) * 16);
        cp_commit();
        cp_wait<0>();
    }
    __syncthreads();

    // ---- persistent Q fragments (hi at +0, lo at +8192) ----
    uint32_t qh[4][4], ql[4][4];
#pragma unroll
    for (int j = 0; j < 4; j++) {
        const uint32_t ad = sbase + (16 * w + pa_row) * 128 + ((32 * j + pa_c) ^ sx);
        ldmx4(qh[j][0], qh[j][1], qh[j][2], qh[j][3], ad);
        ldmx4(ql[j][0], ql[j][1], ql[j][2], ql[j][3], ad + 8192);
    }
    __syncthreads();   // done reading buf0; safe to overwrite with K/V

    const int qrow = qt * TQ + 16 * w + g;
    const float2 qc0 = *(const float2*)(gqs + (size_t)(bb * Lc + qrow) * 2);
    const float2 qc1 = *(const float2*)(gqs + (size_t)(bb * Lc + qrow + 8) * 2);

    float accO[8][4];
#pragma unroll
    for (int n = 0; n < 8; n++)
#pragma unroll
        for (int e = 0; e < 4; e++) accO[n][e] = 0.f;
    float lrow0 = 0.f, lrow1 = 0.f;

    const float2* btab = (const float2*)(smc + OFF_BTB);
    const unsigned char* kbase = &gQKV[1][bh32][0];
    const unsigned char* vbase = &gQKV[2][bh32][0];

    // fetch K/V hi/lo (32KB) + k coords (512B) for tile t into buffer
#define FETCH_TILE(t, bufoff) do {                                             \
        const unsigned char* kb = kbase + (size_t)(t) * 16384;                 \
        const unsigned char* vb = vbase + (size_t)(t) * 16384;                 \
        _Pragma("unroll")                                                      \
        for (int i = 0; i < 8; i++)                                            \
            cp16(sbase + (bufoff) + (tid + 128 * i) * 16,                      \
                 kb + (tid + 128 * i) * 16);                                   \
        _Pragma("unroll")                                                      \
        for (int i = 0; i < 8; i++)                                            \
            cp16(sbase + (bufoff) + 16384 + (tid + 128 * i) * 16,              \
                 vb + (tid + 128 * i) * 16);                                   \
        if (tid < 32)                                                          \
            cp16(sbase + (bufoff) + OFF_KSSR + tid * 16,                       \
                 (const char*)gks + (size_t)(bb * Lc + (t) * 64) * 8 + tid * 16); \
    } while (0)

    FETCH_TILE(0, 0);
    cp_commit();
    FETCH_TILE(1, BUFS);
    cp_commit();

    for (int kt = 0; kt < 32; kt++) {
        cp_wait<1>();      // tile kt landed (kt+1 may still be in flight)
        __syncthreads();
        const uint32_t bo = (kt & 1) ? (uint32_t)BUFS : 0u;

        // ---- S = Q @ K^T : 8 n-tiles, 4 d-chunks, 3 split terms ----
        float cs[8][4];
#pragma unroll
        for (int n = 0; n < 8; n++)
#pragma unroll
            for (int e = 0; e < 4; e++) cs[n][e] = 0.f;

#pragma unroll
        for (int j = 0; j < 4; j++) {
            uint32_t bh2[8][2], bl2[8][2];
#pragma unroll
            for (int p = 0; p < 4; p++) {
                const uint32_t ah2 = sbase + bo + (16 * p + pb_row) * 128
                                     + ((32 * j + pb_c) ^ sx);
                ldmx4(bh2[2 * p][0], bh2[2 * p][1],
                      bh2[2 * p + 1][0], bh2[2 * p + 1][1], ah2);
                ldmx4(bl2[2 * p][0], bl2[2 * p][1],
                      bl2[2 * p + 1][0], bl2[2 * p + 1][1], ah2 + 8192);
            }
#pragma unroll
            for (int n = 0; n < 8; n++) {
                mma16816(cs[n], qh[j], bh2[n][0], bh2[n][1]);
                mma16816(cs[n], ql[j], bh2[n][0], bh2[n][1]);
                mma16816(cs[n], qh[j], bl2[n][0], bl2[n][1]);
            }
        }

        // ---- bias + shifted exp; accumulate row sums ----
        const float2* kss2 = (const float2*)(smc + bo + OFF_KSSR);
        float psum0 = 0.f, psum1 = 0.f;
#pragma unroll
        for (int n = 0; n < 8; n++) {
            const float4 kc = *(const float4*)(kss2 + 8 * n + 2 * tig);
            float bias[4];
            {
                const float dx0 = qc0.x - kc.x, dy0 = qc0.y - kc.y;
                const float dx1 = qc0.x - kc.z, dy1 = qc0.y - kc.w;
                const float dx2 = qc1.x - kc.x, dy2 = qc1.y - kc.y;
                const float dx3 = qc1.x - kc.z, dy3 = qc1.y - kc.w;
                const float dd[4] = {fast_sqrtf(fmaf(dx0, dx0, dy0 * dy0)),
                                     fast_sqrtf(fmaf(dx1, dx1, dy1 * dy1)),
                                     fast_sqrtf(fmaf(dx2, dx2, dy2 * dy2)),
                                     fast_sqrtf(fmaf(dx3, dx3, dy3 * dy3))};
#pragma unroll
                for (int e = 0; e < 4; e++) {
                    const float xi = dd[e] * IDXSCALE;
                    const int   ii = __float2int_rd(xi);
                    const float fr = xi - (float)ii;
                    const float2 tb = btab[ii];
                    bias[e] = fmaf(fr, tb.y, tb.x);
                }
            }
            const float p0 = ex2f(fmaf(cs[n][0], L2E, bias[0]));
            const float p1 = ex2f(fmaf(cs[n][1], L2E, bias[1]));
            const float p2 = ex2f(fmaf(cs[n][2], L2E, bias[2]));
            const float p3 = ex2f(fmaf(cs[n][3], L2E, bias[3]));
            cs[n][0] = p0; cs[n][1] = p1; cs[n][2] = p2; cs[n][3] = p3;
            psum0 += p0 + p1;
            psum1 += p2 + p3;
        }
        lrow0 += psum0;
        lrow1 += psum1;

        // ---- O += P @ V : P frags built in registers from cs ----
#pragma unroll
        for (int j = 0; j < 4; j++) {
            uint32_t vh2[8][2], vl2[8][2];
#pragma unroll
            for (int p = 0; p < 4; p++) {
                const uint32_t ah2 = sbase + bo + 16384 + (16 * j + pa_row) * 128
                                     + ((32 * p + pa_c) ^ sx);
                ldmx4t(vh2[2 * p][0], vh2[2 * p][1],
                       vh2[2 * p + 1][0], vh2[2 * p + 1][1], ah2);
                ldmx4t(vl2[2 * p][0], vl2[2 * p][1],
                       vl2[2 * p + 1][0], vl2[2 * p + 1][1], ah2 + 8192);
            }
            uint32_t pha[4], pla[4];
            pha[0] = pack2(cs[2 * j][0], cs[2 * j][1]);
            pha[1] = pack2(cs[2 * j][2], cs[2 * j][3]);
            pha[2] = pack2(cs[2 * j + 1][0], cs[2 * j + 1][1]);
            pha[3] = pack2(cs[2 * j + 1][2], cs[2 * j + 1][3]);
            pla[0] = pack2(cs[2 * j][0] - lo_f(pha[0]), cs[2 * j][1] - hi_f(pha[0]));
            pla[1] = pack2(cs[2 * j][2] - lo_f(pha[1]), cs[2 * j][3] - hi_f(pha[1]));
            pla[2] = pack2(cs[2 * j + 1][0] - lo_f(pha[2]),
                           cs[2 * j + 1][1] - hi_f(pha[2]));
            pla[3] = pack2(cs[2 * j + 1][2] - lo_f(pha[3]),
                           cs[2 * j + 1][3] - hi_f(pha[3]));
#pragma unroll
            for (int n = 0; n < 8; n++) {
                mma16816(accO[n], pha, vh2[n][0], vh2[n][1]);
                mma16816(accO[n], pla, vh2[n][0], vh2[n][1]);
                mma16816(accO[n], pha, vl2[n][0], vl2[n][1]);
            }
        }

        __syncthreads();   // this buffer's reads complete; safe to refill
        if (kt < 30) FETCH_TILE(kt + 2, bo);
        cp_commit();       // commit (possibly empty) to keep group accounting
    }
#undef FETCH_TILE

    // ---- epilogue: reduce row sums over tig lanes, normalize, store ----
    lrow0 += __shfl_xor_sync(0xffffffffu, lrow0, 1);
    lrow0 += __shfl_xor_sync(0xffffffffu, lrow0, 2);
    lrow1 += __shfl_xor_sync(0xffffffffu, lrow1, 1);
    lrow1 += __shfl_xor_sync(0xffffffffu, lrow1, 2);
    const float inv0 = 1.f / lrow0;
    const float inv1 = 1.f / lrow1;

    float* o0 = gout + ((size_t)((bb * Lc + qrow) * Hc + h)) * 64;
    float* o1 = gout + ((size_t)((bb * Lc + qrow + 8) * Hc + h)) * 64;
#pragma unroll
    for (int n = 0; n < 8; n++) {
        const int dv = 8 * n + 2 * tig;
        *(float2*)(o0 + dv) = make_float2(accO[n][0] * inv0, accO[n][1] * inv0);
        *(float2*)(o1 + dv) = make_float2(accO[n][2] * inv1, accO[n][3] * inv1);
    }
}

extern "C" void kernel_launch(void* const* d_in, const int* in_sizes, int n_in,
                              void* d_out, int out_size)
{
    (void)in_sizes; (void)n_in; (void)out_size;
    const float* qs   = (const float*)d_in[0];
    const float* ks   = (const float*)d_in[1];
    const float* vs   = (const float*)d_in[2];
    const float* qs_s = (const float*)d_in[3];
    const float* ks_s = (const float*)d_in[4];
    const float* a    = (const float*)d_in[5];
    const float* b    = (const float*)d_in[6];
    const float* c    = (const float*)d_in[7];
    float* out = (float*)d_out;

    // pre-pass: split Q/K/V to swizzled bf16 hi/lo tiles
    dim3 pgrid(512, 3);
    tisa_prepass<<<pgrid, 128>>>(qs, ks, vs);

    cudaFuncSetAttribute(tisa_attn_kernel,
                         cudaFuncAttributeMaxDynamicSharedMemorySize, SMEM_BYTES);
    dim3 grid(Lc / TQ, Hc, 2);   // (32, 8, 2) = 512 CTAs
    tisa_attn_kernel<<<grid, 128, SMEM_BYTES>>>(qs_s, ks_s, a, b, c, out);
}

// round 11
// speedup vs baseline: 3.9659x; 1.0537x over previous
#include <cuda_runtime.h>
#include <cuda_fp16.h>
#include <cstdint>
#include <math.h>

// TISA biased attention, round 9: fp16 2-term split mma.sync + xi pre-pass.
//  - QK^T = (q_hi+q_lo) @ k_hi ; O += (p_hi+p_lo) @ v_hi   (fp16, err ~2^-12)
//  - xi = |qs-ks| * IDXSCALE precomputed once per (b,q,k), shared by 8 heads
//  - K/V single fp16 plane: 16KB/tile cp.async double-buffered
//  - Q planes in dedicated smem, frags re-ldmatrix'd per tile (reg relief)
//  - __launch_bounds__(128,4): 4 CTAs/SM -> 512-CTA grid is ONE wave
// B=2, L=2048, H=8, D=64, S=2, F=5. Output fp32 (B,L,H,D).

namespace {
constexpr int Lc = 2048, Hc = 8, Fc = 5;
constexpr int TQ = 64;
constexpr int TBL = 512;
constexpr int OFF_Q  = 0;          // QH 8192 | QL 8192
constexpr int OFF_B0 = 16384;      // buf0: KH 8192 | VH 8192
constexpr int OFF_B1 = 32768;      // buf1
constexpr int BUFS   = 16384;
constexpr int OFF_BTB = 49152;     // 512 x float2
constexpr int SMEM_BYTES = 53248;  // x4 CTA = 208KB <= 228KB
constexpr float DMAX = 1.4142136f;
constexpr float IDXSCALE = (float)(TBL - 1) / DMAX;
constexpr float STEP = DMAX / (float)(TBL - 1);
constexpr float L2E = 1.44269504f;
constexpr float SHIFT = 8.0f;
}

// pre-split tensors: Q hi+lo, K hi, V hi (fp16, ldmatrix-swizzled tiles)
__device__ __align__(16) unsigned char gQ[512][16384];
__device__ __align__(16) unsigned char gK[512][8192];
__device__ __align__(16) unsigned char gV[512][8192];
// xi[b][q][k] = |qs_s - ks_s| * IDXSCALE  (shared across heads)
__device__ __align__(16) float gXi[2][2048][2048];

__device__ __forceinline__ uint32_t smem_u32(const void* p) {
    uint32_t a;
    asm("{ .reg .u64 t; cvta.to.shared.u64 t, %1; cvt.u32.u64 %0, t; }"
        : "=r"(a) : "l"(p));
    return a;
}
__device__ __forceinline__ float fast_sqrtf(float x) {
    float r; asm("sqrt.approx.f32 %0, %1;" : "=f"(r) : "f"(x)); return r;
}
__device__ __forceinline__ float ex2f(float x) {
    float r; asm("ex2.approx.ftz.f32 %0, %1;" : "=f"(r) : "f"(x)); return r;
}
__device__ __forceinline__ uint32_t packh2(float lo, float hi) {
    const __half2 h = __floats2half2_rn(lo, hi);   // .x = lo half
    return *reinterpret_cast<const uint32_t*>(&h);
}
__device__ __forceinline__ float2 unph2(uint32_t u) {
    const __half2 h = *reinterpret_cast<const __half2*>(&u);
    return __half22float2(h);
}

__device__ __forceinline__ void cp16(uint32_t dst, const void* src) {
    asm volatile("cp.async.cg.shared.global [%0], [%1], 16;"
                 :: "r"(dst), "l"(src) : "memory");
}
__device__ __forceinline__ void cp_commit() {
    asm volatile("cp.async.commit_group;" ::: "memory");
}
template <int N>
__device__ __forceinline__ void cp_wait() {
    asm volatile("cp.async.wait_group %0;" :: "n"(N) : "memory");
}

__device__ __forceinline__ void ldmx4(uint32_t& r0, uint32_t& r1,
                                      uint32_t& r2, uint32_t& r3, uint32_t addr) {
    asm volatile("ldmatrix.sync.aligned.m8n8.x4.shared.b16 {%0,%1,%2,%3}, [%4];"
                 : "=r"(r0), "=r"(r1), "=r"(r2), "=r"(r3) : "r"(addr));
}
__device__ __forceinline__ void ldmx4t(uint32_t& r0, uint32_t& r1,
                                       uint32_t& r2, uint32_t& r3, uint32_t addr) {
    asm volatile("ldmatrix.sync.aligned.m8n8.x4.trans.shared.b16 {%0,%1,%2,%3}, [%4];"
                 : "=r"(r0), "=r"(r1), "=r"(r2), "=r"(r3) : "r"(addr));
}
__device__ __forceinline__ void mma16816(float* c, const uint32_t* a,
                                         const uint32_t b0, const uint32_t b1) {
    asm volatile("mma.sync.aligned.m16n8k16.row.col.f32.f16.f16.f32 "
                 "{%0,%1,%2,%3}, {%4,%5,%6,%7}, {%8,%9}, {%0,%1,%2,%3};"
                 : "+f"(c[0]), "+f"(c[1]), "+f"(c[2]), "+f"(c[3])
                 : "r"(a[0]), "r"(a[1]), "r"(a[2]), "r"(a[3]), "r"(b0), "r"(b1));
}

// ------------- pre-pass A: fp32 -> swizzled fp16 tiles (Q split) -------------
__global__ __launch_bounds__(128)
void tisa_prepass_qkv(const float* __restrict__ gq,
                      const float* __restrict__ gk,
                      const float* __restrict__ gv)
{
    __shared__ __align__(16) unsigned char sb[16384];
    const int t3   = blockIdx.y;           // 0=Q,1=K,2=V
    const int idx  = blockIdx.x;           // (b*8+h)*32 + tile
    const int tile = idx & 31;
    const int bh   = idx >> 5;
    const int h    = bh & 7, b = bh >> 3;
    const int tid  = threadIdx.x;
    const int crow = tid & 63;
    const int chalf = (tid >> 6) * 32;

    const float* src = (t3 == 0) ? gq : (t3 == 1) ? gk : gv;
    const float sc = (t3 == 0) ? 0.125f : 1.0f;
    const float* sp = src +
        ((size_t)(((b * Lc + tile * 64 + crow) * Hc) + h)) * 64 + chalf;

#pragma unroll
    for (int jj = 0; jj < 8; jj++) {
        float4 v = *(const float4*)(sp + jj * 4);
        v.x *= sc; v.y *= sc; v.z *= sc; v.w *= sc;
        const uint32_t h0 = packh2(v.x, v.y), h1 = packh2(v.z, v.w);
        const int off = crow * 128 + ((chalf * 2 + jj * 8) ^ ((crow & 7) << 4));
        *(uint2*)(sb + off) = make_uint2(h0, h1);
        if (t3 == 0) {
            const float2 f0 = unph2(h0), f1 = unph2(h1);
            const uint32_t l0 = packh2(v.x - f0.x, v.y - f0.y);
            const uint32_t l1 = packh2(v.z - f1.x, v.w - f1.y);
            *(uint2*)(sb + 8192 + off) = make_uint2(l0, l1);
        }
    }
    __syncthreads();

    const uint4* s4 = (const uint4*)sb;
    if (t3 == 0) {
        uint4* dst = (uint4*)(&gQ[idx][0]);
#pragma unroll
        for (int i = 0; i < 8; i++) dst[tid + 128 * i] = s4[tid + 128 * i];
    } else {
        uint4* dst = (t3 == 1) ? (uint4*)(&gK[idx][0]) : (uint4*)(&gV[idx][0]);
#pragma unroll
        for (int i = 0; i < 4; i++) dst[tid + 128 * i] = s4[tid + 128 * i];
    }
}

// ---------------------- pre-pass B: xi = d * IDXSCALE -----------------------
__global__ __launch_bounds__(256)
void tisa_prepass_xi(const float* __restrict__ gqs,
                     const float* __restrict__ gks)
{
    const int row = blockIdx.x;            // b*2048 + q
    const int b   = row >> 11;
    const float2 qc = *(const float2*)(gqs + (size_t)row * 2);
    const float2* ks2 = (const float2*)(gks + (size_t)b * Lc * 2);
    float* out = &gXi[b][row & 2047][0];
    for (int k = threadIdx.x; k < Lc; k += 256) {
        const float2 kc = ks2[k];
        const float dx = qc.x - kc.x, dy = qc.y - kc.y;
        out[k] = fast_sqrtf(fmaf(dx, dx, dy * dy)) * IDXSCALE;
    }
}

// ------------------------------- main kernel --------------------------------
__global__ __launch_bounds__(128, 4)
void tisa_attn_kernel(const float* __restrict__ ga,
                      const float* __restrict__ gb,
                      const float* __restrict__ gc,
                      float* __restrict__ gout)
{
    extern __shared__ __align__(1024) char smc[];
    const uint32_t sbase = smem_u32(smc);
    const int tid  = threadIdx.x;
    const int w    = tid >> 5;
    const int lane = tid & 31;
    const int g    = lane >> 2;
    const int tig  = lane & 3;
    const int qt   = blockIdx.x;
    const int h    = blockIdx.y;
    const int bb   = blockIdx.z;
    const int bh32 = (bb * Hc + h) * 32;

    const int mrow = lane & 7, msel = lane >> 3;
    const int sx   = mrow << 4;
    const int pa_row = ((msel & 1) << 3) + mrow;
    const int pa_c   = (msel >> 1) << 4;
    const int pb_row = ((msel >> 1) << 3) + mrow;
    const int pb_c   = (msel & 1) << 4;

    // ---- fetch Q planes (16KB) ----
    {
        const unsigned char* qsrc = &gQ[bh32 + qt][0];
#pragma unroll
        for (int i = 0; i < 8; i++)
            cp16(sbase + OFF_Q + (tid + 128 * i) * 16, qsrc + (tid + 128 * i) * 16);
        cp_commit();
    }

    // ---- bias lerp table: (f(d) - SHIFT) * log2e ----
    {
        float2* btab = (float2*)(smc + OFF_BTB);
        float ah[Fc], nb[Fc], ch[Fc];
#pragma unroll
        for (int f = 0; f < Fc; f++) {
            ah[f] = ga[h * Fc + f];
            nb[f] = -fabsf(gb[h * Fc + f]);
            ch[f] = gc[h * Fc + f];
        }
        for (int i = tid; i < TBL; i += 128) {
            const float x0 = i * STEP, x1 = x0 + STEP;
            float f0 = 0.f, f1 = 0.f;
#pragma unroll
            for (int f = 0; f < Fc; f++) {
                const float t0 = x0 - ch[f], t1 = x1 - ch[f];
                f0 = fmaf(ah[f], __expf(nb[f] * t0 * t0), f0);
                f1 = fmaf(ah[f], __expf(nb[f] * t1 * t1), f1);
            }
            btab[i] = make_float2((f0 - SHIFT) * L2E, (f1 - f0) * L2E);
        }
    }

    const int qrow = qt * TQ + 16 * w + g;
    const float* xr0 = &gXi[bb][qrow][0];
    const float* xr1 = &gXi[bb][qrow + 8][0];

    float accO[8][4];
#pragma unroll
    for (int n = 0; n < 8; n++)
#pragma unroll
        for (int e = 0; e < 4; e++) accO[n][e] = 0.f;
    float lrow0 = 0.f, lrow1 = 0.f;

    const float2* btab = (const float2*)(smc + OFF_BTB);
    const unsigned char* kbase = &gK[bh32][0];
    const unsigned char* vbase = &gV[bh32][0];

    // fetch K,V fp16 planes (16KB) for tile t into buffer
#define FETCH_TILE(t, bufoff) do {                                             \
        const unsigned char* kb = kbase + (size_t)(t) * 8192;                  \
        const unsigned char* vb = vbase + (size_t)(t) * 8192;                  \
        _Pragma("unroll")                                                      \
        for (int i = 0; i < 4; i++)                                            \
            cp16(sbase + (bufoff) + (tid + 128 * i) * 16,                      \
                 kb + (tid + 128 * i) * 16);                                   \
        _Pragma("unroll")                                                      \
        for (int i = 0; i < 4; i++)                                            \
            cp16(sbase + (bufoff) + 8192 + (tid + 128 * i) * 16,               \
                 vb + (tid + 128 * i) * 16);                                   \
    } while (0)

    FETCH_TILE(0, OFF_B0);
    cp_commit();
    FETCH_TILE(1, OFF_B1);
    cp_commit();
    // groups in flight: [Q][K0V0][K1V1]

    for (int kt = 0; kt < 32; kt++) {
        cp_wait<1>();
        __syncthreads();
        const uint32_t bo = (kt & 1) ? (uint32_t)OFF_B1 : (uint32_t)OFF_B0;

        // ---- S = (q_hi + q_lo) @ k_hi ----
        float cs[8][4];
#pragma unroll
        for (int n = 0; n < 8; n++)
#pragma unroll
            for (int e = 0; e < 4; e++) cs[n][e] = 0.f;

#pragma unroll
        for (int j = 0; j < 4; j++) {
            uint32_t qhf[4], qlf[4];
            const uint32_t aq = sbase + OFF_Q + (16 * w + pa_row) * 128
                                + ((32 * j + pa_c) ^ sx);
            ldmx4(qhf[0], qhf[1], qhf[2], qhf[3], aq);
            ldmx4(qlf[0], qlf[1], qlf[2], qlf[3], aq + 8192);
            uint32_t bh2[8][2];
#pragma unroll
            for (int p = 0; p < 4; p++) {
                const uint32_t ak = sbase + bo + (16 * p + pb_row) * 128
                                    + ((32 * j + pb_c) ^ sx);
                ldmx4(bh2[2 * p][0], bh2[2 * p][1],
                      bh2[2 * p + 1][0], bh2[2 * p + 1][1], ak);
            }
#pragma unroll
            for (int n = 0; n < 8; n++) {
                mma16816(cs[n], qhf, bh2[n][0], bh2[n][1]);
                mma16816(cs[n], qlf, bh2[n][0], bh2[n][1]);
            }
        }

        // ---- bias (xi lookup) + shifted exp; accumulate row sums ----
        const int kcol0 = kt * 64 + 2 * tig;
        float psum0 = 0.f, psum1 = 0.f;
#pragma unroll
        for (int n = 0; n < 8; n++) {
            const float2 xa = *(const float2*)(xr0 + kcol0 + 8 * n);
            const float2 xb = *(const float2*)(xr1 + kcol0 + 8 * n);
            const float xi4[4] = {xa.x, xa.y, xb.x, xb.y};
            float bias[4];
#pragma unroll
            for (int e = 0; e < 4; e++) {
                const int   ii = __float2int_rd(xi4[e]);
                const float fr = xi4[e] - (float)ii;
                const float2 tb = btab[ii];
                bias[e] = fmaf(fr, tb.y, tb.x);
            }
            const float p0 = ex2f(fmaf(cs[n][0], L2E, bias[0]));
            const float p1 = ex2f(fmaf(cs[n][1], L2E, bias[1]));
            const float p2 = ex2f(fmaf(cs[n][2], L2E, bias[2]));
            const float p3 = ex2f(fmaf(cs[n][3], L2E, bias[3]));
            cs[n][0] = p0; cs[n][1] = p1; cs[n][2] = p2; cs[n][3] = p3;
            psum0 += p0 + p1;
            psum1 += p2 + p3;
        }
        lrow0 += psum0;
        lrow1 += psum1;

        // ---- O += (p_hi + p_lo) @ v_hi ----
#pragma unroll
        for (int j = 0; j < 4; j++) {
            uint32_t vh2[8][2];
#pragma unroll
            for (int p = 0; p < 4; p++) {
                const uint32_t av = sbase + bo + 8192 + (16 * j + pa_row) * 128
                                    + ((32 * p + pa_c) ^ sx);
                ldmx4t(vh2[2 * p][0], vh2[2 * p][1],
                       vh2[2 * p + 1][0], vh2[2 * p + 1][1], av);
            }
            uint32_t pha[4], pla[4];
            pha[0] = packh2(cs[2 * j][0], cs[2 * j][1]);
            pha[1] = packh2(cs[2 * j][2], cs[2 * j][3]);
            pha[2] = packh2(cs[2 * j + 1][0], cs[2 * j + 1][1]);
            pha[3] = packh2(cs[2 * j + 1][2], cs[2 * j + 1][3]);
            {
                const float2 f0 = unph2(pha[0]), f1 = unph2(pha[1]);
                const float2 f2 = unph2(pha[2]), f3 = unph2(pha[3]);
                pla[0] = packh2(cs[2 * j][0] - f0.x, cs[2 * j][1] - f0.y);
                pla[1] = packh2(cs[2 * j][2] - f1.x, cs[2 * j][3] - f1.y);
                pla[2] = packh2(cs[2 * j + 1][0] - f2.x, cs[2 * j + 1][1] - f2.y);
                pla[3] = packh2(cs[2 * j + 1][2] - f3.x, cs[2 * j + 1][3] - f3.y);
            }
#pragma unroll
            for (int n = 0; n < 8; n++) {
                mma16816(accO[n], pha, vh2[n][0], vh2[n][1]);
                mma16816(accO[n], pla, vh2[n][0], vh2[n][1]);
            }
        }

        __syncthreads();
        if (kt < 30) FETCH_TILE(kt + 2, bo);
        cp_commit();
    }
#undef FETCH_TILE

    // ---- epilogue ----
    lrow0 += __shfl_xor_sync(0xffffffffu, lrow0, 1);
    lrow0 += __shfl_xor_sync(0xffffffffu, lrow0, 2);
    lrow1 += __shfl_xor_sync(0xffffffffu, lrow1, 1);
    lrow1 += __shfl_xor_sync(0xffffffffu, lrow1, 2);
    const float inv0 = 1.f / lrow0;
    const float inv1 = 1.f / lrow1;

    float* o0 = gout + ((size_t)((bb * Lc + qrow) * Hc + h)) * 64;
    float* o1 = gout + ((size_t)((bb * Lc + qrow + 8) * Hc + h)) * 64;
#pragma unroll
    for (int n = 0; n < 8; n++) {
        const int dv = 8 * n + 2 * tig;
        *(float2*)(o0 + dv) = make_float2(accO[n][0] * inv0, accO[n][1] * inv0);
        *(float2*)(o1 + dv) = make_float2(accO[n][2] * inv1, accO[n][3] * inv1);
    }
}

extern "C" void kernel_launch(void* const* d_in, const int* in_sizes, int n_in,
                              void* d_out, int out_size)
{
    (void)in_sizes; (void)n_in; (void)out_size;
    const float* qs   = (const float*)d_in[0];
    const float* ks   = (const float*)d_in[1];
    const float* vs   = (const float*)d_in[2];
    const float* qs_s = (const float*)d_in[3];
    const float* ks_s = (const float*)d_in[4];
    const float* a    = (const float*)d_in[5];
    const float* b    = (const float*)d_in[6];
    const float* c    = (const float*)d_in[7];
    float* out = (float*)d_out;

    dim3 pgrid(512, 3);
    tisa_prepass_qkv<<<pgrid, 128>>>(qs, ks, vs);
    tisa_prepass_xi<<<4096, 256>>>(qs_s, ks_s);

    cudaFuncSetAttribute(tisa_attn_kernel,
                         cudaFuncAttributeMaxDynamicSharedMemorySize, SMEM_BYTES);
    dim3 grid(Lc / TQ, Hc, 2);   // 512 CTAs, single wave at occ 4
    tisa_attn_kernel<<<grid, 128, SMEM_BYTES>>>(a, b, c, out);
}